// round 5
// baseline (speedup 1.0000x reference)
#include <cuda_runtime.h>
#include <stdint.h>

// B=16, N=2048 for this problem instance.
__device__ unsigned char g_keep[16 * 2048];   // keep[b][n]
__device__ int           g_ready[16];         // per-batch release flag (memset to 0 per launch)

// ---------------------------------------------------------------------------
// Fused kernel. Grid = B*N/2 blocks (one per PAIR of adjacent rows), 256 thr.
//   - all blocks: prefetch their 4 float4 of adj (loads in flight)
//   - blocks 0..B-1: radix-select top-k for batch=bid (exact lax.top_k set),
//     publish g_keep, fence, set g_ready[bid]
//   - all blocks: spin on g_ready[their batch], fence, apply row/col mask
// Deadlock-free: bids 0..15 are wave-1 resident (deterministic bid->SM map).
// ---------------------------------------------------------------------------
__global__ void __launch_bounds__(256)
fused_topk_mask_kernel(const float4* __restrict__ adj,
                       const float*  __restrict__ score,
                       float4* __restrict__ out, int N, int k, int B) {
    const int tid  = threadIdx.x;
    const int nvec = N >> 2;                 // float4 per row (512)
    const int pairPerBatch = N >> 1;

    int r  = blockIdx.x;                     // pair index
    int b  = r / pairPerBatch;
    int i0 = (r - b * pairPerBatch) * 2;
    int i1 = i0 + 1;

    size_t base0 = ((size_t)b * N + i0) * nvec;
    size_t base1 = base0 + nvec;

    int j0 = tid, j1 = tid + 256;            // nvec=512 exactly covered

    // ---- prefetch: 4 front-batched global loads ----
    float4 v00 = adj[base0 + j0];
    float4 v01 = adj[base0 + j1];
    float4 v10 = adj[base1 + j0];
    float4 v11 = adj[base1 + j1];

    // ---- blocks 0..B-1: exact top-k radix select for batch = blockIdx.x ----
    if (blockIdx.x < (unsigned)B) {
        __shared__ unsigned u[2048];
        __shared__ unsigned hist[256];
        __shared__ unsigned sscan[256];
        __shared__ unsigned s_prefix, s_kk;

        const int bb = blockIdx.x;
        const float* sc = score + (size_t)bb * N;

        for (int t = tid; t < N; t += 256) {
            unsigned x = __float_as_uint(sc[t]);
            x ^= (x & 0x80000000u) ? 0xFFFFFFFFu : 0x80000000u;  // order-preserving
            u[t] = x;
        }
        if (tid == 0) { s_prefix = 0u; s_kk = (unsigned)k; }
        __syncthreads();

        for (int shift = 24; shift >= 0; shift -= 8) {
            unsigned prefix = s_prefix;
            unsigned kk     = s_kk;
            unsigned pmask  = (shift == 24) ? 0u : (0xFFFFFFFFu << (shift + 8));

            hist[tid] = 0u;
            __syncthreads();
            for (int t = tid; t < N; t += 256) {
                unsigned x = u[t];
                if ((x & pmask) == prefix)
                    atomicAdd(&hist[(x >> shift) & 0xFFu], 1u);
            }
            __syncthreads();

            // inclusive suffix-sum over 256 bins (Hillis-Steele)
            sscan[tid] = hist[255 - tid];
            __syncthreads();
#pragma unroll
            for (int off = 1; off < 256; off <<= 1) {
                unsigned add = (tid >= off) ? sscan[tid - off] : 0u;
                __syncthreads();
                sscan[tid] += add;
                __syncthreads();
            }

            {
                int bin = 255 - tid;
                unsigned incl = sscan[tid];
                unsigned excl = incl - hist[bin];
                if (excl < kk && incl >= kk) {       // unique bin
                    s_prefix = prefix | ((unsigned)bin << shift);
                    s_kk     = kk - excl;
                }
            }
            __syncthreads();
        }

        unsigned T        = s_prefix;        // exact k-th largest pattern
        unsigned need_eq  = s_kk;            // equals to keep (>=1)
        unsigned total_eq = hist[T & 0xFFu]; // exact equal count

        for (int t = tid; t < N; t += 256) {
            unsigned x = u[t];
            unsigned char kp = 0u;
            if (x > T) {
                kp = 1u;
            } else if (x == T) {
                if (total_eq == need_eq) {
                    kp = 1u;                 // common path
                } else {
                    unsigned c = 0u;         // rare tie path: rank by index
                    for (int j = 0; j < t; j++) c += (u[j] == T);
                    kp = (c < need_eq) ? 1u : 0u;
                }
            }
            g_keep[bb * N + t] = kp;
        }

        __threadfence();
        __syncthreads();
        if (tid == 0) ((volatile int*)g_ready)[bb] = 1;
    }

    // ---- wait for this batch's keep mask (overlaps the in-flight loads) ----
    if (tid == 0) {
        while (((volatile int*)g_ready)[b] == 0) __nanosleep(64);
    }
    __syncthreads();
    __threadfence();

    const unsigned char* kb = g_keep + b * N;
    const uchar4*        km = (const uchar4*)kb;   // 2KB, L1/L2-resident
    bool kept0 = (kb[i0] != 0);
    bool kept1 = (kb[i1] != 0);
    uchar4 m0 = km[j0];
    uchar4 m1 = km[j1];

    if (!kept0) {
        v00.x = m0.x ? v00.x : 0.0f;  v00.y = m0.y ? v00.y : 0.0f;
        v00.z = m0.z ? v00.z : 0.0f;  v00.w = m0.w ? v00.w : 0.0f;
        v01.x = m1.x ? v01.x : 0.0f;  v01.y = m1.y ? v01.y : 0.0f;
        v01.z = m1.z ? v01.z : 0.0f;  v01.w = m1.w ? v01.w : 0.0f;
    }
    if (!kept1) {
        v10.x = m0.x ? v10.x : 0.0f;  v10.y = m0.y ? v10.y : 0.0f;
        v10.z = m0.z ? v10.z : 0.0f;  v10.w = m0.w ? v10.w : 0.0f;
        v11.x = m1.x ? v11.x : 0.0f;  v11.y = m1.y ? v11.y : 0.0f;
        v11.z = m1.z ? v11.z : 0.0f;  v11.w = m1.w ? v11.w : 0.0f;
    }
    out[base0 + j0] = v00;
    out[base0 + j1] = v01;
    out[base1 + j0] = v10;
    out[base1 + j1] = v11;
}

extern "C" void kernel_launch(void* const* d_in, const int* in_sizes, int n_in,
                              void* d_out, int out_size) {
    const float* adj   = (const float*)d_in[0];   // [B, N, N] fp32
    const float* score = (const float*)d_in[1];   // [B, N, 1] fp32

    long long n_adj   = in_sizes[0];
    long long n_score = in_sizes[1];
    int N = (int)(n_adj / n_score);               // 2048
    int B = (int)(n_score / N);                   // 16
    int k = N / 2;                                // RATE = 0.5

    // clear release flags (graph-capturable memset node, no allocation)
    void* flags = nullptr;
    cudaGetSymbolAddress(&flags, g_ready);
    cudaMemsetAsync(flags, 0, sizeof(int) * 16, 0);

    fused_topk_mask_kernel<<<B * N / 2, 256>>>(
        (const float4*)adj, score, (float4*)d_out, N, k, B);
}

// round 6
// speedup vs baseline: 1.0580x; 1.0580x over previous
#include <cuda_runtime.h>
#include <stdint.h>

// keep[b][n] = 1 if node n is in the top-k of batch b. B=16, N=2048.
__device__ unsigned char g_keep[16 * 2048];

// ---------------------------------------------------------------------------
// Kernel 1: exact top-k via 8-bit radix select.
// Bin suffix-scan done by ONE WARP with shfl (no block barriers in the scan):
// lane l owns reversed bins r=8l..8l+7 (bin=255-r); local prefix + warp scan.
// Keep set: u > T, plus need_eq lowest-index elements with u == T.
// Bit-exact vs jax.lax.top_k (value desc, ties -> lower index).
// One block per batch, 512 threads. Ends with PDL trigger.
// ---------------------------------------------------------------------------
__global__ void __launch_bounds__(512)
topk_radix_kernel(const float* __restrict__ score, int N, int k) {
    __shared__ unsigned u[2048];
    __shared__ unsigned hist[256];
    __shared__ unsigned s_prefix, s_kk;

    const int b   = blockIdx.x;
    const int tid = threadIdx.x;
    const float* sc = score + (size_t)b * N;

    for (int t = tid; t < N; t += 512) {
        unsigned x = __float_as_uint(sc[t]);
        x ^= (x & 0x80000000u) ? 0xFFFFFFFFu : 0x80000000u;  // order-preserving
        u[t] = x;
    }
    if (tid == 0) { s_prefix = 0u; s_kk = (unsigned)k; }
    __syncthreads();

    for (int shift = 24; shift >= 0; shift -= 8) {
        const unsigned prefix = s_prefix;
        const unsigned kk     = s_kk;
        const unsigned pmask  = (shift == 24) ? 0u : (0xFFFFFFFFu << (shift + 8));

        if (tid < 256) hist[tid] = 0u;
        __syncthreads();

        for (int t = tid; t < N; t += 512) {
            unsigned x = u[t];
            if ((x & pmask) == prefix)
                atomicAdd(&hist[(x >> shift) & 0xFFu], 1u);
        }
        __syncthreads();

        // single-warp suffix scan over 256 bins: r = 255 - bin
        if (tid < 32) {
            unsigned v[8], p[8];
            unsigned acc = 0u;
#pragma unroll
            for (int i = 0; i < 8; i++) {
                v[i] = hist[255 - (tid * 8 + i)];
                acc += v[i];
                p[i] = acc;                       // lane-local inclusive prefix
            }
            // warp exclusive scan of lane totals (acc)
            unsigned lane_excl = 0u, run = acc;
#pragma unroll
            for (int off = 1; off < 32; off <<= 1) {
                unsigned n0 = __shfl_up_sync(0xFFFFFFFFu, run, off);
                if ((int)(tid) >= off) { lane_excl += n0; run += n0; }
            }
            // incl(r) = lane_excl + p[i]; excl(r) = incl - v[i]
#pragma unroll
            for (int i = 0; i < 8; i++) {
                unsigned incl = lane_excl + p[i];
                unsigned excl = incl - v[i];
                if (excl < kk && incl >= kk) {    // unique r
                    int bin = 255 - (tid * 8 + i);
                    s_prefix = prefix | ((unsigned)bin << shift);
                    s_kk     = kk - excl;
                }
            }
        }
        __syncthreads();
    }

    const unsigned T        = s_prefix;          // exact k-th largest pattern
    const unsigned need_eq  = s_kk;              // equals to keep (>=1)
    const unsigned total_eq = hist[T & 0xFFu];   // exact equal count (last level)

    for (int t = tid; t < N; t += 512) {
        unsigned x = u[t];
        unsigned char kp = 0u;
        if (x > T) {
            kp = 1u;
        } else if (x == T) {
            if (total_eq == need_eq) {
                kp = 1u;                         // common path: keep all equals
            } else {
                unsigned c = 0u;                 // rare: rank among equals by index
                for (int j = 0; j < t; j++) c += (u[j] == T);
                kp = (c < need_eq) ? 1u : 0u;
            }
        }
        g_keep[b * N + t] = kp;
    }

    __threadfence();
    __syncthreads();
    if (tid == 0) cudaTriggerProgrammaticLaunchCompletion();
}

// ---------------------------------------------------------------------------
// Kernel 2: out[b,i,j] = adj[b,i,j] * (keep[b,i] || keep[b,j])
// PDL secondary (unchanged from R4: 75.6us @ 80.3% DRAM): prefetch adj BEFORE
// cudaGridDependencySynchronize() so launch latency + wave-1 loads overlap topk.
// ---------------------------------------------------------------------------
__global__ void apply_mask_kernel(const float4* __restrict__ adj,
                                  float4* __restrict__ out, int N) {
    int row = blockIdx.x;              // 0 .. B*N-1
    int b   = row / N;
    int i   = row - b * N;

    int    nvec = N >> 2;
    size_t base = (size_t)row * nvec;

    int  j0 = threadIdx.x;
    int  j1 = threadIdx.x + blockDim.x;
    bool h0 = j0 < nvec;
    bool h1 = j1 < nvec;

    float4 v0 = {0,0,0,0}, v1 = {0,0,0,0};
    if (h0) v0 = adj[base + j0];
    if (h1) v1 = adj[base + j1];

    cudaGridDependencySynchronize();   // wait for g_keep (overlapped w/ loads)

    const unsigned char* kb = g_keep + b * N;
    const uchar4*        km = (const uchar4*)kb;  // 2KB, L1-resident
    bool row_kept = (kb[i] != 0);

    if (!row_kept) {
        if (h0) {
            uchar4 m = km[j0];
            v0.x = m.x ? v0.x : 0.0f;  v0.y = m.y ? v0.y : 0.0f;
            v0.z = m.z ? v0.z : 0.0f;  v0.w = m.w ? v0.w : 0.0f;
        }
        if (h1) {
            uchar4 m = km[j1];
            v1.x = m.x ? v1.x : 0.0f;  v1.y = m.y ? v1.y : 0.0f;
            v1.z = m.z ? v1.z : 0.0f;  v1.w = m.w ? v1.w : 0.0f;
        }
    }
    if (h0) out[base + j0] = v0;
    if (h1) out[base + j1] = v1;

    // generic tail (unused for N=2048 with 256 threads)
    for (int j = threadIdx.x + 2 * blockDim.x; j < nvec; j += blockDim.x) {
        float4 v = adj[base + j];
        if (!row_kept) {
            uchar4 m = km[j];
            v.x = m.x ? v.x : 0.0f;  v.y = m.y ? v.y : 0.0f;
            v.z = m.z ? v.z : 0.0f;  v.w = m.w ? v.w : 0.0f;
        }
        out[base + j] = v;
    }
}

extern "C" void kernel_launch(void* const* d_in, const int* in_sizes, int n_in,
                              void* d_out, int out_size) {
    const float* adj   = (const float*)d_in[0];   // [B, N, N] fp32
    const float* score = (const float*)d_in[1];   // [B, N, 1] fp32

    long long n_adj   = in_sizes[0];
    long long n_score = in_sizes[1];
    int N = (int)(n_adj / n_score);               // 2048
    int B = (int)(n_score / N);                   // 16
    int k = N / 2;                                // RATE = 0.5

    topk_radix_kernel<<<B, 512>>>(score, N, k);

    // Secondary with Programmatic Stream Serialization (PDL).
    cudaLaunchConfig_t cfg = {};
    cfg.gridDim  = dim3((unsigned)(B * N));
    cfg.blockDim = dim3(256);
    cfg.stream   = 0;
    cudaLaunchAttribute attr[1];
    attr[0].id = cudaLaunchAttributeProgrammaticStreamSerialization;
    attr[0].val.programmaticStreamSerializationAllowed = 1;
    cfg.attrs    = attr;
    cfg.numAttrs = 1;
    cudaLaunchKernelEx(&cfg, apply_mask_kernel,
                       (const float4*)adj, (float4*)d_out, N);
}